// round 14
// baseline (speedup 1.0000x reference)
#include <cuda_runtime.h>
#include <cuda_fp16.h>
#include <math.h>

// Problem constants
#define BB   4
#define SEQ  2048
#define DIM  512
#define NH   8
#define DH   64
#define ROWS (BB * SEQ)   // 8192
#define HID  512
#define QKVS 1536         // packed qkv row stride

// Scratch (device globals; no runtime allocation)
__device__ __half g_xn  [ROWS * DIM];
__device__ __half g_qkv [ROWS * QKVS];
__device__ __half g_ao  [ROWS * HID];
__device__ __half g_wqkv[DIM * QKVS];
__device__ __half g_wo  [HID * DIM];

// ---------------------------------------------------------------------------
// helpers
// ---------------------------------------------------------------------------
__device__ __forceinline__ unsigned smem_u32(const void* p) {
    return (unsigned)__cvta_generic_to_shared(p);
}

#define LDSM4(d0,d1,d2,d3,addr) \
    asm volatile("ldmatrix.sync.aligned.m8n8.x4.shared.b16 {%0,%1,%2,%3}, [%4];" \
        : "=r"(d0), "=r"(d1), "=r"(d2), "=r"(d3) : "r"(addr))

#define LDSM4T(d0,d1,d2,d3,addr) \
    asm volatile("ldmatrix.sync.aligned.m8n8.x4.trans.shared.b16 {%0,%1,%2,%3}, [%4];" \
        : "=r"(d0), "=r"(d1), "=r"(d2), "=r"(d3) : "r"(addr))

__device__ __forceinline__ void mma16816(float* c, const unsigned* a,
                                         unsigned b0, unsigned b1) {
    asm volatile(
        "mma.sync.aligned.m16n8k16.row.col.f32.f16.f16.f32 "
        "{%0,%1,%2,%3}, {%4,%5,%6,%7}, {%8,%9}, {%0,%1,%2,%3};"
        : "+f"(c[0]), "+f"(c[1]), "+f"(c[2]), "+f"(c[3])
        : "r"(a[0]), "r"(a[1]), "r"(a[2]), "r"(a[3]), "r"(b0), "r"(b1));
}

__device__ __forceinline__ void mma16816h(unsigned* c, const unsigned* a,
                                          unsigned b0, unsigned b1) {
    asm volatile(
        "mma.sync.aligned.m16n8k16.row.col.f16.f16.f16.f16 "
        "{%0,%1}, {%2,%3,%4,%5}, {%6,%7}, {%0,%1};"
        : "+r"(c[0]), "+r"(c[1])
        : "r"(a[0]), "r"(a[1]), "r"(a[2]), "r"(a[3]), "r"(b0), "r"(b1));
}

__device__ __forceinline__ unsigned h2exp2u(unsigned x) {
    unsigned y;
    asm("ex2.approx.f16x2 %0, %1;" : "=r"(y) : "r"(x));
    return y;
}

__device__ __forceinline__ void cp_async16(unsigned saddr, const void* gptr) {
    asm volatile("cp.async.cg.shared.global [%0], [%1], 16;" :: "r"(saddr), "l"(gptr));
}
#define CP_COMMIT() asm volatile("cp.async.commit_group;")

// ---------------------------------------------------------------------------
// prep kernel: weight convert + LayerNorm in ONE launch.
// grid = (2048, 5). grid.y 0..2: W{q,k,v} -> wqkv (512 blocks used);
// grid.y 3: Wo -> wo (512 blocks used); grid.y 4: LayerNorm (4 rows/block).
// ---------------------------------------------------------------------------
#define QSCALE 0.06376529780930452f   // 512^-0.5 * log2(e)

__global__ __launch_bounds__(128) void prep_kernel(
    const float* __restrict__ Wq, const float* __restrict__ Wk,
    const float* __restrict__ Wv, const float* __restrict__ Wo,
    __half* __restrict__ wqkv, __half* __restrict__ wo,
    const float* __restrict__ x, const float* __restrict__ gw,
    const float* __restrict__ bw, __half* __restrict__ xn)
{
    const int m = blockIdx.y;
    if (m < 4) {
        if (blockIdx.x >= 512) return;
        int i = (blockIdx.x * 128 + threadIdx.x) * 4;
        if (m < 3) {
            const float* src = (m == 0) ? Wq : (m == 1) ? Wk : Wv;
            float sc = (m == 0) ? QSCALE : 1.f;
            float4 v = *(const float4*)(src + i);
            int row = i >> 9, col = i & 511;
            __half2* dst = (__half2*)(wqkv + (size_t)row * QKVS + m * 512 + col);
            dst[0] = __floats2half2_rn(v.x * sc, v.y * sc);
            dst[1] = __floats2half2_rn(v.z * sc, v.w * sc);
        } else {
            float4 v = *(const float4*)(Wo + i);
            *(__half2*)(wo + i)     = __floats2half2_rn(v.x, v.y);
            *(__half2*)(wo + i + 2) = __floats2half2_rn(v.z, v.w);
        }
        return;
    }

    // LayerNorm: one warp per row, 4 rows per block
    const int warp = threadIdx.x >> 5;
    const int lane = threadIdx.x & 31;
    const int row  = blockIdx.x * 4 + warp;
    const float* xr = x + (size_t)row * DIM;

    float v[16];
    float s = 0.f, ss = 0.f;
#pragma unroll
    for (int i = 0; i < 4; i++) {
        float4 v4 = *(const float4*)(xr + lane * 4 + i * 128);
        v[i*4+0] = v4.x; v[i*4+1] = v4.y; v[i*4+2] = v4.z; v[i*4+3] = v4.w;
        s  += v4.x + v4.y + v4.z + v4.w;
        ss += v4.x*v4.x + v4.y*v4.y + v4.z*v4.z + v4.w*v4.w;
    }
#pragma unroll
    for (int o = 16; o; o >>= 1) {
        s  += __shfl_xor_sync(0xffffffffu, s,  o);
        ss += __shfl_xor_sync(0xffffffffu, ss, o);
    }
    float mu   = s * (1.f / DIM);
    float var  = ss * (1.f / DIM) - mu * mu;
    float rstd = rsqrtf(var + 1e-5f);

    __half* orow = xn + (size_t)row * DIM;
#pragma unroll
    for (int i = 0; i < 4; i++) {
        int d = lane * 4 + i * 128;
        float4 g4 = *(const float4*)(gw + d);
        float4 b4 = *(const float4*)(bw + d);
        __half2 h0 = __floats2half2_rn((v[i*4+0] - mu) * rstd * g4.x + b4.x,
                                       (v[i*4+1] - mu) * rstd * g4.y + b4.y);
        __half2 h1 = __floats2half2_rn((v[i*4+2] - mu) * rstd * g4.z + b4.z,
                                       (v[i*4+3] - mu) * rstd * g4.w + b4.w);
        *(__half2*)(orow + d)     = h0;
        *(__half2*)(orow + d + 2) = h1;
    }
}

// ---------------------------------------------------------------------------
// HGEMM v5: C = A[M,K] @ B[K,N], 128x128 tile, BK=64, 512 threads
// (16 warps: 4m x 4n, warp tile 32x32), 3-stage cp.async ring.
// Same tile/traffic geometry as the round-12 best, but 16 warps -> 4
// warps/SMSP to cover the ~8cyc HMMA rt and barrier gaps.
// Ch fp16 out, or Cf fp32 out with +bias +resid.
// ---------------------------------------------------------------------------
#define GBM 128
#define GBN 128
#define GBK 64
#define APITCH 72    // 64+8 halfs, 144B rows, conflict-free
#define BPITCH 136   // 128+8 halfs, 272B rows
#define HG_STAGE_H (GBM * APITCH + GBK * BPITCH)   // 9216 + 8704 = 17920 halfs
#define HG_SMEM    (3 * HG_STAGE_H * 2)            // 107520 B

__global__ __launch_bounds__(512, 1) void hgemm_kernel(
    const __half* __restrict__ A, const __half* __restrict__ B,
    __half* __restrict__ Ch, float* __restrict__ Cf,
    int M, int N, int K,
    const float* __restrict__ bias, const float* __restrict__ resid)
{
    extern __shared__ __half hsm[];

    const int tid  = threadIdx.x;
    const int warp = tid >> 5;
    const int lane = tid & 31;
    const int warp_m = warp >> 2;   // 0..3
    const int warp_n = warp & 3;    // 0..3
    const int row0 = blockIdx.y * GBM;
    const int col0 = blockIdx.x * GBN;

    const unsigned hbase = smem_u32(hsm);

    float acc[2][4][4];
#pragma unroll
    for (int mi = 0; mi < 2; mi++)
#pragma unroll
        for (int nf = 0; nf < 4; nf++)
#pragma unroll
            for (int j = 0; j < 4; j++) acc[mi][nf][j] = 0.f;

    const int nk = K / GBK;   // 8

    // per-stage layout: A tile [128][72] then B tile [64][136]
#define HG_LOAD(k0, s) do {                                                   \
    unsigned _ab = hbase + (s) * HG_STAGE_H * 2;                              \
    unsigned _bb = _ab + GBM * APITCH * 2;                                    \
    _Pragma("unroll")                                                         \
    for (int _j = 0; _j < 2; _j++) {                                          \
        int _i = tid + 512 * _j;                                              \
        int _ar = _i >> 3;                                                    \
        int _ac = (_i & 7) * 8;                                               \
        cp_async16(_ab + (_ar * APITCH + _ac) * 2,                            \
                   A + (size_t)(row0 + _ar) * K + (k0) + _ac);                \
        int _br = _i >> 4;                                                    \
        int _bc = (_i & 15) * 8;                                              \
        cp_async16(_bb + (_br * BPITCH + _bc) * 2,                            \
                   B + (size_t)((k0) + _br) * N + col0 + _bc);                \
    }                                                                         \
} while (0)

    HG_LOAD(0, 0);       CP_COMMIT();
    HG_LOAD(GBK, 1);     CP_COMMIT();

    const int a_rr = (lane & 15);
    const int a_cc = (lane & 16) ? 8 : 0;

    int st = 0, st_nxt = 2;
    for (int kt = 0; kt < nk; kt++) {
        asm volatile("cp.async.wait_group 1;");
        __syncthreads();

        if (kt + 2 < nk) {
            HG_LOAD((kt + 2) * GBK, st_nxt);
            CP_COMMIT();
        } else {
            CP_COMMIT();
        }

        const unsigned ab = hbase + st * HG_STAGE_H * 2;
        const unsigned bb = ab + GBM * APITCH * 2;

#pragma unroll
        for (int kc = 0; kc < 4; kc++) {
            unsigned af[2][4];
#pragma unroll
            for (int mi = 0; mi < 2; mi++) {
                unsigned addr = ab +
                    ((warp_m * 32 + mi * 16 + a_rr) * APITCH + kc * 16 + a_cc) * 2;
                LDSM4(af[mi][0], af[mi][1], af[mi][2], af[mi][3], addr);
            }
            unsigned b0, b1, b2, b3, c0, c1, c2, c3;
            unsigned baddr = bb +
                ((kc * 16 + a_rr) * BPITCH + warp_n * 32 + a_cc) * 2;
            LDSM4T(b0, b1, b2, b3, baddr);
            LDSM4T(c0, c1, c2, c3, baddr + 32);   // +16 halfs
#pragma unroll
            for (int mi = 0; mi < 2; mi++) {
                mma16816(acc[mi][0], af[mi], b0, b1);
                mma16816(acc[mi][1], af[mi], b2, b3);
                mma16816(acc[mi][2], af[mi], c0, c1);
                mma16816(acc[mi][3], af[mi], c2, c3);
            }
        }
        st = (st == 2) ? 0 : st + 1;
        st_nxt = (st_nxt == 2) ? 0 : st_nxt + 1;
    }
#undef HG_LOAD

    const int g  = lane >> 2;
    const int tg = lane & 3;
#pragma unroll
    for (int mi = 0; mi < 2; mi++) {
        int r0 = row0 + warp_m * 32 + mi * 16 + g;
        int r1 = r0 + 8;
#pragma unroll
        for (int nf = 0; nf < 4; nf++) {
            int c = col0 + warp_n * 32 + nf * 8 + tg * 2;
            float v0 = acc[mi][nf][0];
            float v1 = acc[mi][nf][1];
            float v2 = acc[mi][nf][2];
            float v3 = acc[mi][nf][3];
            if (Cf) {
                float2 o0, o1;
                o0.x = v0 + bias[c]     + resid[(size_t)r0 * N + c];
                o0.y = v1 + bias[c + 1] + resid[(size_t)r0 * N + c + 1];
                o1.x = v2 + bias[c]     + resid[(size_t)r1 * N + c];
                o1.y = v3 + bias[c + 1] + resid[(size_t)r1 * N + c + 1];
                *(float2*)(Cf + (size_t)r0 * N + c) = o0;
                *(float2*)(Cf + (size_t)r1 * N + c) = o1;
            } else {
                *(__half2*)(Ch + (size_t)r0 * N + c) =
                    __floats2half2_rn(v0, v1);
                *(__half2*)(Ch + (size_t)r1 * N + c) =
                    __floats2half2_rn(v2, v3);
            }
        }
    }
}

// ---------------------------------------------------------------------------
// Flash attention v6 (round-9 winner, unchanged):
// 128 threads = 4 warps, 32 queries/warp (128 q/CTA). Each K/V B-fragment
// feeds TWO A-fragments. Fixed-max softmax via ex2.f16x2 on f16-accum S
// frags, l via P @ ones MMA, 3-stage cp.async KV ring, 3 CTAs/SM.
// ---------------------------------------------------------------------------
#define PITCH   72
#define BIAS_H2 0xC5C5C5C5u   // half2(-5.7695 ~ -4*log2e) uniform -> cancels
#define ONES2   0x3C003C00u
#define FLASH_SMEM (3 * 2 * 64 * PITCH * 2)   // 55296 B

__global__ __launch_bounds__(128, 3) void flash_mma_kernel(
    const __half* __restrict__ qkv, __half* __restrict__ Op)
{
    extern __shared__ __half fsm[];

    const int tid  = threadIdx.x;
    const int warp = tid >> 5;
    const int lane = tid & 31;
    const int g    = lane >> 2;
    const int tg   = lane & 3;

    const int m0 = blockIdx.x * 128;
    const int h  = blockIdx.y;
    const int b  = blockIdx.z;

    const size_t rowbase = (size_t)b * SEQ;
    const int    colbase = h * DH;

    const __half* Qg = qkv + colbase;
    const __half* Kg = qkv + 512  + colbase;
    const __half* Vg = qkv + 1024 + colbase;

    const int r16 = tid >> 3;         // 0..15
    const int c8  = (tid & 7) * 8;

    // ---- Q tile: 128 rows into ring area (transient) ----
#pragma unroll
    for (int p = 0; p < 8; p++) {
        int row = p * 16 + r16;
        cp_async16(smem_u32(fsm + (size_t)row * PITCH + c8),
                   Qg + (rowbase + m0 + row) * QKVS + c8);
    }
    CP_COMMIT();
    asm volatile("cp.async.wait_group 0;");
    __syncthreads();

    unsigned qf[2][4][4];
    {
        int cc_off = (lane & 16) ? 8 : 0;
#pragma unroll
        for (int mi = 0; mi < 2; mi++) {
            int rr = warp * 32 + mi * 16 + (lane & 15);
#pragma unroll
            for (int kc = 0; kc < 4; kc++) {
                unsigned addr = smem_u32(fsm + (size_t)rr * PITCH + kc * 16 + cc_off);
                LDSM4(qf[mi][kc][0], qf[mi][kc][1], qf[mi][kc][2], qf[mi][kc][3], addr);
            }
        }
    }
    __syncthreads();   // qf extracted before KV overwrites

    float o[2][8][4];
#pragma unroll
    for (int mi = 0; mi < 2; mi++)
#pragma unroll
        for (int nc = 0; nc < 8; nc++)
#pragma unroll
            for (int j = 0; j < 4; j++) o[mi][nc][j] = 0.f;
    float lf[2][4] = {{0.f,0.f,0.f,0.f},{0.f,0.f,0.f,0.f}};

    const int k_rr_off = (lane & 7) + ((lane & 16) ? 8 : 0);
    const int k_cc_off = (lane & 8) ? 8 : 0;
    const int v_rr_off = (lane & 15);
    const int v_cc_off = (lane & 16) ? 8 : 0;

    const int NT = SEQ / 64;   // 32

    // prologue: tiles 0,1 into stages 0,1
#pragma unroll
    for (int pt = 0; pt < 2; pt++) {
#pragma unroll
        for (int p = 0; p < 4; p++) {
            int row = p * 16 + r16;
            size_t goff = (rowbase + pt * 64 + row) * QKVS + c8;
            cp_async16(smem_u32(fsm + ((size_t)(pt * 2 + 0) * 64 + row) * PITCH + c8),
                       Kg + goff);
            cp_async16(smem_u32(fsm + ((size_t)(pt * 2 + 1) * 64 + row) * PITCH + c8),
                       Vg + goff);
        }
        CP_COMMIT();
    }

    for (int kt = 0; kt < NT; kt++) {
        const int st = kt % 3;
        asm volatile("cp.async.wait_group 1;");
        __syncthreads();

        if (kt + 2 < NT) {
            const int sn = (kt + 2) % 3;
            const int n2 = (kt + 2) * 64;
#pragma unroll
            for (int p = 0; p < 4; p++) {
                int row = p * 16 + r16;
                size_t goff = (rowbase + n2 + row) * QKVS + c8;
                cp_async16(smem_u32(fsm + ((size_t)(sn * 2 + 0) * 64 + row) * PITCH + c8),
                           Kg + goff);
                cp_async16(smem_u32(fsm + ((size_t)(sn * 2 + 1) * 64 + row) * PITCH + c8),
                           Vg + goff);
            }
            CP_COMMIT();
        } else {
            CP_COMMIT();
        }

        const __half* Kst = fsm + (size_t)(st * 2 + 0) * 64 * PITCH;
        const __half* Vst = fsm + (size_t)(st * 2 + 1) * 64 * PITCH;

        // S + exp per key-group (keeps S liveness to 8 regs)
        unsigned pf[2][4][4];
#pragma unroll
        for (int kg = 0; kg < 4; kg++) {
            unsigned shl[2][2][2];
#pragma unroll
            for (int mi = 0; mi < 2; mi++) {
                shl[mi][0][0] = BIAS_H2; shl[mi][0][1] = BIAS_H2;
                shl[mi][1][0] = BIAS_H2; shl[mi][1][1] = BIAS_H2;
            }
#pragma unroll
            for (int kc = 0; kc < 4; kc++) {
                unsigned kb0, kb1, kb2, kb3;
                unsigned addr = smem_u32(
                    Kst + (size_t)(kg * 16 + k_rr_off) * PITCH + kc * 16 + k_cc_off);
                LDSM4(kb0, kb1, kb2, kb3, addr);
                mma16816h(shl[0][0], qf[0][kc], kb0, kb1);
                mma16816h(shl[0][1], qf[0][kc], kb2, kb3);
                mma16816h(shl[1][0], qf[1][kc], kb0, kb1);
                mma16816h(shl[1][1], qf[1][kc], kb2, kb3);
            }
#pragma unroll
            for (int mi = 0; mi < 2; mi++) {
                pf[mi][kg][0] = h2exp2u(shl[mi][0][0]);
                pf[mi][kg][1] = h2exp2u(shl[mi][0][1]);
                pf[mi][kg][2] = h2exp2u(shl[mi][1][0]);
                pf[mi][kg][3] = h2exp2u(shl[mi][1][1]);
                mma16816(lf[mi], pf[mi][kg], ONES2, ONES2);
            }
        }

        // O += P @ V (V fragment reused across mi)
#pragma unroll
        for (int kc = 0; kc < 4; kc++) {
#pragma unroll
            for (int dg = 0; dg < 4; dg++) {
                unsigned vb0, vb1, vb2, vb3;
                unsigned addr = smem_u32(
                    Vst + (size_t)(kc * 16 + v_rr_off) * PITCH + dg * 16 + v_cc_off);
                LDSM4T(vb0, vb1, vb2, vb3, addr);
                mma16816(o[0][2 * dg + 0], pf[0][kc], vb0, vb1);
                mma16816(o[0][2 * dg + 1], pf[0][kc], vb2, vb3);
                mma16816(o[1][2 * dg + 0], pf[1][kc], vb0, vb1);
                mma16816(o[1][2 * dg + 1], pf[1][kc], vb2, vb3);
            }
        }
    }

#pragma unroll
    for (int mi = 0; mi < 2; mi++) {
        float inv0 = 1.f / lf[mi][0];
        float inv1 = 1.f / lf[mi][2];
        int row0 = m0 + warp * 32 + mi * 16 + g;
        int row1 = row0 + 8;
#pragma unroll
        for (int nc = 0; nc < 8; nc++) {
            int col = colbase + nc * 8 + tg * 2;
            *(__half2*)(Op + (rowbase + row0) * HID + col) =
                __floats2half2_rn(o[mi][nc][0] * inv0, o[mi][nc][1] * inv0);
            *(__half2*)(Op + (rowbase + row1) * HID + col) =
                __floats2half2_rn(o[mi][nc][2] * inv1, o[mi][nc][3] * inv1);
        }
    }
}

// ---------------------------------------------------------------------------
extern "C" void kernel_launch(void* const* d_in, const int* in_sizes, int n_in,
                              void* d_out, int out_size)
{
    const float* x    = (const float*)d_in[0];
    const float* ln_g = (const float*)d_in[1];
    const float* ln_b = (const float*)d_in[2];
    const float* Wq   = (const float*)d_in[3];
    const float* Wk   = (const float*)d_in[4];
    const float* Wv   = (const float*)d_in[5];
    const float* Wo   = (const float*)d_in[6];
    const float* bo   = (const float*)d_in[7];
    float* out = (float*)d_out;

    __half *xn, *qkv, *ao, *wqkv, *wo;
    cudaGetSymbolAddress((void**)&xn,   g_xn);
    cudaGetSymbolAddress((void**)&qkv,  g_qkv);
    cudaGetSymbolAddress((void**)&ao,   g_ao);
    cudaGetSymbolAddress((void**)&wqkv, g_wqkv);
    cudaGetSymbolAddress((void**)&wo,   g_wo);

    cudaFuncSetAttribute(flash_mma_kernel,
                         cudaFuncAttributeMaxDynamicSharedMemorySize, FLASH_SMEM);
    cudaFuncSetAttribute(hgemm_kernel,
                         cudaFuncAttributeMaxDynamicSharedMemorySize, HG_SMEM);

    // 0+1) weight convert + LayerNorm, single launch
    prep_kernel<<<dim3(2048, 5), 128>>>(Wq, Wk, Wv, Wo, wqkv, wo,
                                        x, ln_g, ln_b, xn);

    // 2) fused QKV projection: [8192,512] @ [512,1536]
    hgemm_kernel<<<dim3(QKVS / GBN, ROWS / GBM), 512, HG_SMEM>>>(
        xn, wqkv, qkv, nullptr, ROWS, QKVS, DIM, nullptr, nullptr);

    // 3) Flash attention -> fp16
    flash_mma_kernel<<<dim3(SEQ / 128, NH, BB), 128, FLASH_SMEM>>>(qkv, ao);

    // 4) Output projection + bias + residual (fp32 out)
    hgemm_kernel<<<dim3(DIM / GBN, ROWS / GBM), 512, HG_SMEM>>>(
        ao, wo, nullptr, out, ROWS, DIM, HID, bo, x);
}

// round 15
// speedup vs baseline: 1.1174x; 1.1174x over previous
#include <cuda_runtime.h>
#include <cuda_fp16.h>
#include <math.h>

// Problem constants
#define BB   4
#define SEQ  2048
#define DIM  512
#define NH   8
#define DH   64
#define ROWS (BB * SEQ)   // 8192
#define HID  512
#define QKVS 1536         // packed qkv row stride

// Scratch (device globals; no runtime allocation)
__device__ __half g_xn  [ROWS * DIM];
__device__ __half g_qkv [ROWS * QKVS];
__device__ __half g_ao  [ROWS * HID];
__device__ __half g_wqkv[DIM * QKVS];
__device__ __half g_wo  [HID * DIM];

// ---------------------------------------------------------------------------
// helpers
// ---------------------------------------------------------------------------
__device__ __forceinline__ unsigned smem_u32(const void* p) {
    return (unsigned)__cvta_generic_to_shared(p);
}

#define LDSM4(d0,d1,d2,d3,addr) \
    asm volatile("ldmatrix.sync.aligned.m8n8.x4.shared.b16 {%0,%1,%2,%3}, [%4];" \
        : "=r"(d0), "=r"(d1), "=r"(d2), "=r"(d3) : "r"(addr))

#define LDSM4T(d0,d1,d2,d3,addr) \
    asm volatile("ldmatrix.sync.aligned.m8n8.x4.trans.shared.b16 {%0,%1,%2,%3}, [%4];" \
        : "=r"(d0), "=r"(d1), "=r"(d2), "=r"(d3) : "r"(addr))

__device__ __forceinline__ void mma16816(float* c, const unsigned* a,
                                         unsigned b0, unsigned b1) {
    asm volatile(
        "mma.sync.aligned.m16n8k16.row.col.f32.f16.f16.f32 "
        "{%0,%1,%2,%3}, {%4,%5,%6,%7}, {%8,%9}, {%0,%1,%2,%3};"
        : "+f"(c[0]), "+f"(c[1]), "+f"(c[2]), "+f"(c[3])
        : "r"(a[0]), "r"(a[1]), "r"(a[2]), "r"(a[3]), "r"(b0), "r"(b1));
}

__device__ __forceinline__ void mma16816h(unsigned* c, const unsigned* a,
                                          unsigned b0, unsigned b1) {
    asm volatile(
        "mma.sync.aligned.m16n8k16.row.col.f16.f16.f16.f16 "
        "{%0,%1}, {%2,%3,%4,%5}, {%6,%7}, {%0,%1};"
        : "+r"(c[0]), "+r"(c[1])
        : "r"(a[0]), "r"(a[1]), "r"(a[2]), "r"(a[3]), "r"(b0), "r"(b1));
}

__device__ __forceinline__ unsigned h2exp2u(unsigned x) {
    unsigned y;
    asm("ex2.approx.f16x2 %0, %1;" : "=r"(y) : "r"(x));
    return y;
}

__device__ __forceinline__ void cp_async16(unsigned saddr, const void* gptr) {
    asm volatile("cp.async.cg.shared.global [%0], [%1], 16;" :: "r"(saddr), "l"(gptr));
}
#define CP_COMMIT() asm volatile("cp.async.commit_group;")

// ---------------------------------------------------------------------------
// prep kernel: weight convert + LayerNorm in ONE launch.
// grid = (2048, 5). grid.y 0..2: W{q,k,v} -> wqkv (512 blocks used);
// grid.y 3: Wo -> wo (512 blocks used); grid.y 4: LayerNorm (4 rows/block).
// ---------------------------------------------------------------------------
#define QSCALE 0.06376529780930452f   // 512^-0.5 * log2(e)

__global__ __launch_bounds__(128) void prep_kernel(
    const float* __restrict__ Wq, const float* __restrict__ Wk,
    const float* __restrict__ Wv, const float* __restrict__ Wo,
    __half* __restrict__ wqkv, __half* __restrict__ wo,
    const float* __restrict__ x, const float* __restrict__ gw,
    const float* __restrict__ bw, __half* __restrict__ xn)
{
    const int m = blockIdx.y;
    if (m < 4) {
        if (blockIdx.x >= 512) return;
        int i = (blockIdx.x * 128 + threadIdx.x) * 4;
        if (m < 3) {
            const float* src = (m == 0) ? Wq : (m == 1) ? Wk : Wv;
            float sc = (m == 0) ? QSCALE : 1.f;
            float4 v = *(const float4*)(src + i);
            int row = i >> 9, col = i & 511;
            __half2* dst = (__half2*)(wqkv + (size_t)row * QKVS + m * 512 + col);
            dst[0] = __floats2half2_rn(v.x * sc, v.y * sc);
            dst[1] = __floats2half2_rn(v.z * sc, v.w * sc);
        } else {
            float4 v = *(const float4*)(Wo + i);
            *(__half2*)(wo + i)     = __floats2half2_rn(v.x, v.y);
            *(__half2*)(wo + i + 2) = __floats2half2_rn(v.z, v.w);
        }
        return;
    }

    // LayerNorm: one warp per row, 4 rows per block
    const int warp = threadIdx.x >> 5;
    const int lane = threadIdx.x & 31;
    const int row  = blockIdx.x * 4 + warp;
    const float* xr = x + (size_t)row * DIM;

    float v[16];
    float s = 0.f, ss = 0.f;
#pragma unroll
    for (int i = 0; i < 4; i++) {
        float4 v4 = *(const float4*)(xr + lane * 4 + i * 128);
        v[i*4+0] = v4.x; v[i*4+1] = v4.y; v[i*4+2] = v4.z; v[i*4+3] = v4.w;
        s  += v4.x + v4.y + v4.z + v4.w;
        ss += v4.x*v4.x + v4.y*v4.y + v4.z*v4.z + v4.w*v4.w;
    }
#pragma unroll
    for (int o = 16; o; o >>= 1) {
        s  += __shfl_xor_sync(0xffffffffu, s,  o);
        ss += __shfl_xor_sync(0xffffffffu, ss, o);
    }
    float mu   = s * (1.f / DIM);
    float var  = ss * (1.f / DIM) - mu * mu;
    float rstd = rsqrtf(var + 1e-5f);

    __half* orow = xn + (size_t)row * DIM;
#pragma unroll
    for (int i = 0; i < 4; i++) {
        int d = lane * 4 + i * 128;
        float4 g4 = *(const float4*)(gw + d);
        float4 b4 = *(const float4*)(bw + d);
        __half2 h0 = __floats2half2_rn((v[i*4+0] - mu) * rstd * g4.x + b4.x,
                                       (v[i*4+1] - mu) * rstd * g4.y + b4.y);
        __half2 h1 = __floats2half2_rn((v[i*4+2] - mu) * rstd * g4.z + b4.z,
                                       (v[i*4+3] - mu) * rstd * g4.w + b4.w);
        *(__half2*)(orow + d)     = h0;
        *(__half2*)(orow + d + 2) = h1;
    }
}

// ---------------------------------------------------------------------------
// HGEMM v6: C = A[M,K] @ B[K,N], 128x128 tile, BK=64, 256 threads
// (8 warps: 2m x 4n, warp tile 64x32), 3-stage cp.async ring.
// f16 ACCUMULATORS (packed h2): acc 64->32 regs -> ~100 regs/thread ->
// 2 independent CTAs/SM (215KB smem, <=128 regs) = 4 warps/SMSP of
// unsynchronized work. K=512 fp16 accumulation error ~0.3% on sigma=1
// values -> final rel_err ~1e-4 (budget 1e-3).
// Ch fp16 out (direct h2 store), or Cf fp32 out with +bias +resid.
// ---------------------------------------------------------------------------
#define GBM 128
#define GBN 128
#define GBK 64
#define APITCH 72    // 64+8 halfs, 144B rows
#define BPITCH 136   // 128+8 halfs, 272B rows
#define HG_STAGE_H (GBM * APITCH + GBK * BPITCH)   // 17920 halfs
#define HG_SMEM    (3 * HG_STAGE_H * 2)            // 107520 B

__global__ __launch_bounds__(256, 2) void hgemm_kernel(
    const __half* __restrict__ A, const __half* __restrict__ B,
    __half* __restrict__ Ch, float* __restrict__ Cf,
    int M, int N, int K,
    const float* __restrict__ bias, const float* __restrict__ resid)
{
    extern __shared__ __half hsm[];

    const int tid  = threadIdx.x;
    const int warp = tid >> 5;
    const int lane = tid & 31;
    const int warp_m = warp >> 2;   // 0..1
    const int warp_n = warp & 3;    // 0..3
    const int row0 = blockIdx.y * GBM;
    const int col0 = blockIdx.x * GBN;

    const unsigned hbase = smem_u32(hsm);

    // f16 accumulators: [mi][nf][0]=rows g (2 cols packed), [1]=rows g+8
    unsigned acc[4][4][2];
#pragma unroll
    for (int mi = 0; mi < 4; mi++)
#pragma unroll
        for (int nf = 0; nf < 4; nf++) { acc[mi][nf][0] = 0u; acc[mi][nf][1] = 0u; }

    const int nk = K / GBK;   // 8

#define HG_LOAD(k0, s) do {                                                   \
    unsigned _ab = hbase + (s) * HG_STAGE_H * 2;                              \
    unsigned _bb = _ab + GBM * APITCH * 2;                                    \
    _Pragma("unroll")                                                         \
    for (int _j = 0; _j < 4; _j++) {                                          \
        int _i = tid + 256 * _j;                                              \
        int _ar = _i >> 3;                                                    \
        int _ac = (_i & 7) * 8;                                               \
        cp_async16(_ab + (_ar * APITCH + _ac) * 2,                            \
                   A + (size_t)(row0 + _ar) * K + (k0) + _ac);                \
        int _br = _i >> 4;                                                    \
        int _bc = (_i & 15) * 8;                                              \
        cp_async16(_bb + (_br * BPITCH + _bc) * 2,                            \
                   B + (size_t)((k0) + _br) * N + col0 + _bc);                \
    }                                                                         \
} while (0)

    HG_LOAD(0, 0);       CP_COMMIT();
    HG_LOAD(GBK, 1);     CP_COMMIT();

    const int a_rr = (lane & 15);
    const int a_cc = (lane & 16) ? 8 : 0;

    int st = 0, st_nxt = 2;
    for (int kt = 0; kt < nk; kt++) {
        asm volatile("cp.async.wait_group 1;");
        __syncthreads();

        if (kt + 2 < nk) {
            HG_LOAD((kt + 2) * GBK, st_nxt);
            CP_COMMIT();
        } else {
            CP_COMMIT();
        }

        const unsigned ab = hbase + st * HG_STAGE_H * 2;
        const unsigned bb = ab + GBM * APITCH * 2;

#pragma unroll
        for (int kc = 0; kc < 4; kc++) {
            unsigned af[4][4];
#pragma unroll
            for (int mi = 0; mi < 4; mi++) {
                unsigned addr = ab +
                    ((warp_m * 64 + mi * 16 + a_rr) * APITCH + kc * 16 + a_cc) * 2;
                LDSM4(af[mi][0], af[mi][1], af[mi][2], af[mi][3], addr);
            }
            unsigned b0, b1, b2, b3, c0, c1, c2, c3;
            unsigned baddr = bb +
                ((kc * 16 + a_rr) * BPITCH + warp_n * 32 + a_cc) * 2;
            LDSM4T(b0, b1, b2, b3, baddr);
            LDSM4T(c0, c1, c2, c3, baddr + 32);   // +16 halfs
#pragma unroll
            for (int mi = 0; mi < 4; mi++) {
                mma16816h(acc[mi][0], af[mi], b0, b1);
                mma16816h(acc[mi][1], af[mi], b2, b3);
                mma16816h(acc[mi][2], af[mi], c0, c1);
                mma16816h(acc[mi][3], af[mi], c2, c3);
            }
        }
        st = (st == 2) ? 0 : st + 1;
        st_nxt = (st_nxt == 2) ? 0 : st_nxt + 1;
    }
#undef HG_LOAD

    const int g  = lane >> 2;
    const int tg = lane & 3;
#pragma unroll
    for (int mi = 0; mi < 4; mi++) {
        int r0 = row0 + warp_m * 64 + mi * 16 + g;
        int r1 = r0 + 8;
#pragma unroll
        for (int nf = 0; nf < 4; nf++) {
            int c = col0 + warp_n * 32 + nf * 8 + tg * 2;
            if (Cf) {
                float2 f0 = __half22float2(*(__half2*)&acc[mi][nf][0]);
                float2 f1 = __half22float2(*(__half2*)&acc[mi][nf][1]);
                float2 o0, o1;
                o0.x = f0.x + bias[c]     + resid[(size_t)r0 * N + c];
                o0.y = f0.y + bias[c + 1] + resid[(size_t)r0 * N + c + 1];
                o1.x = f1.x + bias[c]     + resid[(size_t)r1 * N + c];
                o1.y = f1.y + bias[c + 1] + resid[(size_t)r1 * N + c + 1];
                *(float2*)(Cf + (size_t)r0 * N + c) = o0;
                *(float2*)(Cf + (size_t)r1 * N + c) = o1;
            } else {
                // f16 C-frag is already the packed pair
                *(unsigned*)(Ch + (size_t)r0 * N + c) = acc[mi][nf][0];
                *(unsigned*)(Ch + (size_t)r1 * N + c) = acc[mi][nf][1];
            }
        }
    }
}

// ---------------------------------------------------------------------------
// Flash attention v6 (round-9 winner, unchanged):
// 128 threads = 4 warps, 32 queries/warp (128 q/CTA). Each K/V B-fragment
// feeds TWO A-fragments. Fixed-max softmax via ex2.f16x2 on f16-accum S
// frags, l via P @ ones MMA, 3-stage cp.async KV ring, 3 CTAs/SM.
// ---------------------------------------------------------------------------
#define PITCH   72
#define BIAS_H2 0xC5C5C5C5u   // half2(-5.7695 ~ -4*log2e) uniform -> cancels
#define ONES2   0x3C003C00u
#define FLASH_SMEM (3 * 2 * 64 * PITCH * 2)   // 55296 B

__global__ __launch_bounds__(128, 3) void flash_mma_kernel(
    const __half* __restrict__ qkv, __half* __restrict__ Op)
{
    extern __shared__ __half fsm[];

    const int tid  = threadIdx.x;
    const int warp = tid >> 5;
    const int lane = tid & 31;
    const int g    = lane >> 2;
    const int tg   = lane & 3;

    const int m0 = blockIdx.x * 128;
    const int h  = blockIdx.y;
    const int b  = blockIdx.z;

    const size_t rowbase = (size_t)b * SEQ;
    const int    colbase = h * DH;

    const __half* Qg = qkv + colbase;
    const __half* Kg = qkv + 512  + colbase;
    const __half* Vg = qkv + 1024 + colbase;

    const int r16 = tid >> 3;         // 0..15
    const int c8  = (tid & 7) * 8;

    // ---- Q tile: 128 rows into ring area (transient) ----
#pragma unroll
    for (int p = 0; p < 8; p++) {
        int row = p * 16 + r16;
        cp_async16(smem_u32(fsm + (size_t)row * PITCH + c8),
                   Qg + (rowbase + m0 + row) * QKVS + c8);
    }
    CP_COMMIT();
    asm volatile("cp.async.wait_group 0;");
    __syncthreads();

    unsigned qf[2][4][4];
    {
        int cc_off = (lane & 16) ? 8 : 0;
#pragma unroll
        for (int mi = 0; mi < 2; mi++) {
            int rr = warp * 32 + mi * 16 + (lane & 15);
#pragma unroll
            for (int kc = 0; kc < 4; kc++) {
                unsigned addr = smem_u32(fsm + (size_t)rr * PITCH + kc * 16 + cc_off);
                LDSM4(qf[mi][kc][0], qf[mi][kc][1], qf[mi][kc][2], qf[mi][kc][3], addr);
            }
        }
    }
    __syncthreads();   // qf extracted before KV overwrites

    float o[2][8][4];
#pragma unroll
    for (int mi = 0; mi < 2; mi++)
#pragma unroll
        for (int nc = 0; nc < 8; nc++)
#pragma unroll
            for (int j = 0; j < 4; j++) o[mi][nc][j] = 0.f;
    float lf[2][4] = {{0.f,0.f,0.f,0.f},{0.f,0.f,0.f,0.f}};

    const int k_rr_off = (lane & 7) + ((lane & 16) ? 8 : 0);
    const int k_cc_off = (lane & 8) ? 8 : 0;
    const int v_rr_off = (lane & 15);
    const int v_cc_off = (lane & 16) ? 8 : 0;

    const int NT = SEQ / 64;   // 32

    // prologue: tiles 0,1 into stages 0,1
#pragma unroll
    for (int pt = 0; pt < 2; pt++) {
#pragma unroll
        for (int p = 0; p < 4; p++) {
            int row = p * 16 + r16;
            size_t goff = (rowbase + pt * 64 + row) * QKVS + c8;
            cp_async16(smem_u32(fsm + ((size_t)(pt * 2 + 0) * 64 + row) * PITCH + c8),
                       Kg + goff);
            cp_async16(smem_u32(fsm + ((size_t)(pt * 2 + 1) * 64 + row) * PITCH + c8),
                       Vg + goff);
        }
        CP_COMMIT();
    }

    for (int kt = 0; kt < NT; kt++) {
        const int st = kt % 3;
        asm volatile("cp.async.wait_group 1;");
        __syncthreads();

        if (kt + 2 < NT) {
            const int sn = (kt + 2) % 3;
            const int n2 = (kt + 2) * 64;
#pragma unroll
            for (int p = 0; p < 4; p++) {
                int row = p * 16 + r16;
                size_t goff = (rowbase + n2 + row) * QKVS + c8;
                cp_async16(smem_u32(fsm + ((size_t)(sn * 2 + 0) * 64 + row) * PITCH + c8),
                           Kg + goff);
                cp_async16(smem_u32(fsm + ((size_t)(sn * 2 + 1) * 64 + row) * PITCH + c8),
                           Vg + goff);
            }
            CP_COMMIT();
        } else {
            CP_COMMIT();
        }

        const __half* Kst = fsm + (size_t)(st * 2 + 0) * 64 * PITCH;
        const __half* Vst = fsm + (size_t)(st * 2 + 1) * 64 * PITCH;

        // S + exp per key-group (keeps S liveness to 8 regs)
        unsigned pf[2][4][4];
#pragma unroll
        for (int kg = 0; kg < 4; kg++) {
            unsigned shl[2][2][2];
#pragma unroll
            for (int mi = 0; mi < 2; mi++) {
                shl[mi][0][0] = BIAS_H2; shl[mi][0][1] = BIAS_H2;
                shl[mi][1][0] = BIAS_H2; shl[mi][1][1] = BIAS_H2;
            }
#pragma unroll
            for (int kc = 0; kc < 4; kc++) {
                unsigned kb0, kb1, kb2, kb3;
                unsigned addr = smem_u32(
                    Kst + (size_t)(kg * 16 + k_rr_off) * PITCH + kc * 16 + k_cc_off);
                LDSM4(kb0, kb1, kb2, kb3, addr);
                mma16816h(shl[0][0], qf[0][kc], kb0, kb1);
                mma16816h(shl[0][1], qf[0][kc], kb2, kb3);
                mma16816h(shl[1][0], qf[1][kc], kb0, kb1);
                mma16816h(shl[1][1], qf[1][kc], kb2, kb3);
            }
#pragma unroll
            for (int mi = 0; mi < 2; mi++) {
                pf[mi][kg][0] = h2exp2u(shl[mi][0][0]);
                pf[mi][kg][1] = h2exp2u(shl[mi][0][1]);
                pf[mi][kg][2] = h2exp2u(shl[mi][1][0]);
                pf[mi][kg][3] = h2exp2u(shl[mi][1][1]);
                mma16816(lf[mi], pf[mi][kg], ONES2, ONES2);
            }
        }

        // O += P @ V (V fragment reused across mi)
#pragma unroll
        for (int kc = 0; kc < 4; kc++) {
#pragma unroll
            for (int dg = 0; dg < 4; dg++) {
                unsigned vb0, vb1, vb2, vb3;
                unsigned addr = smem_u32(
                    Vst + (size_t)(kc * 16 + v_rr_off) * PITCH + dg * 16 + v_cc_off);
                LDSM4T(vb0, vb1, vb2, vb3, addr);
                mma16816(o[0][2 * dg + 0], pf[0][kc], vb0, vb1);
                mma16816(o[0][2 * dg + 1], pf[0][kc], vb2, vb3);
                mma16816(o[1][2 * dg + 0], pf[1][kc], vb0, vb1);
                mma16816(o[1][2 * dg + 1], pf[1][kc], vb2, vb3);
            }
        }
    }

#pragma unroll
    for (int mi = 0; mi < 2; mi++) {
        float inv0 = 1.f / lf[mi][0];
        float inv1 = 1.f / lf[mi][2];
        int row0 = m0 + warp * 32 + mi * 16 + g;
        int row1 = row0 + 8;
#pragma unroll
        for (int nc = 0; nc < 8; nc++) {
            int col = colbase + nc * 8 + tg * 2;
            *(__half2*)(Op + (rowbase + row0) * HID + col) =
                __floats2half2_rn(o[mi][nc][0] * inv0, o[mi][nc][1] * inv0);
            *(__half2*)(Op + (rowbase + row1) * HID + col) =
                __floats2half2_rn(o[mi][nc][2] * inv1, o[mi][nc][3] * inv1);
        }
    }
}

// ---------------------------------------------------------------------------
extern "C" void kernel_launch(void* const* d_in, const int* in_sizes, int n_in,
                              void* d_out, int out_size)
{
    const float* x    = (const float*)d_in[0];
    const float* ln_g = (const float*)d_in[1];
    const float* ln_b = (const float*)d_in[2];
    const float* Wq   = (const float*)d_in[3];
    const float* Wk   = (const float*)d_in[4];
    const float* Wv   = (const float*)d_in[5];
    const float* Wo   = (const float*)d_in[6];
    const float* bo   = (const float*)d_in[7];
    float* out = (float*)d_out;

    __half *xn, *qkv, *ao, *wqkv, *wo;
    cudaGetSymbolAddress((void**)&xn,   g_xn);
    cudaGetSymbolAddress((void**)&qkv,  g_qkv);
    cudaGetSymbolAddress((void**)&ao,   g_ao);
    cudaGetSymbolAddress((void**)&wqkv, g_wqkv);
    cudaGetSymbolAddress((void**)&wo,   g_wo);

    cudaFuncSetAttribute(flash_mma_kernel,
                         cudaFuncAttributeMaxDynamicSharedMemorySize, FLASH_SMEM);
    cudaFuncSetAttribute(hgemm_kernel,
                         cudaFuncAttributeMaxDynamicSharedMemorySize, HG_SMEM);

    // 0+1) weight convert + LayerNorm, single launch
    prep_kernel<<<dim3(2048, 5), 128>>>(Wq, Wk, Wv, Wo, wqkv, wo,
                                        x, ln_g, ln_b, xn);

    // 2) fused QKV projection: [8192,512] @ [512,1536]
    hgemm_kernel<<<dim3(QKVS / GBN, ROWS / GBM), 256, HG_SMEM>>>(
        xn, wqkv, qkv, nullptr, ROWS, QKVS, DIM, nullptr, nullptr);

    // 3) Flash attention -> fp16
    flash_mma_kernel<<<dim3(SEQ / 128, NH, BB), 128, FLASH_SMEM>>>(qkv, ao);

    // 4) Output projection + bias + residual (fp32 out)
    hgemm_kernel<<<dim3(DIM / GBN, ROWS / GBM), 256, HG_SMEM>>>(
        ao, wo, nullptr, out, ROWS, DIM, HID, bo, x);
}

// round 17
// speedup vs baseline: 1.1303x; 1.0115x over previous
#include <cuda_runtime.h>
#include <cuda_fp16.h>
#include <math.h>

// Problem constants
#define BB   4
#define SEQ  2048
#define DIM  512
#define NH   8
#define DH   64
#define ROWS (BB * SEQ)   // 8192
#define HID  512
#define QKVS 1536         // packed qkv row stride

// Scratch (device globals; no runtime allocation)
__device__ __half g_xn  [ROWS * DIM];
__device__ __half g_qkv [ROWS * QKVS];
__device__ __half g_ao  [ROWS * HID];
__device__ __half g_wqkv[DIM * QKVS];
__device__ __half g_wo  [HID * DIM];

// ---------------------------------------------------------------------------
// helpers
// ---------------------------------------------------------------------------
__device__ __forceinline__ unsigned smem_u32(const void* p) {
    return (unsigned)__cvta_generic_to_shared(p);
}

#define LDSM4(d0,d1,d2,d3,addr) \
    asm volatile("ldmatrix.sync.aligned.m8n8.x4.shared.b16 {%0,%1,%2,%3}, [%4];" \
        : "=r"(d0), "=r"(d1), "=r"(d2), "=r"(d3) : "r"(addr))

#define LDSM4T(d0,d1,d2,d3,addr) \
    asm volatile("ldmatrix.sync.aligned.m8n8.x4.trans.shared.b16 {%0,%1,%2,%3}, [%4];" \
        : "=r"(d0), "=r"(d1), "=r"(d2), "=r"(d3) : "r"(addr))

__device__ __forceinline__ void mma16816(float* c, const unsigned* a,
                                         unsigned b0, unsigned b1) {
    asm volatile(
        "mma.sync.aligned.m16n8k16.row.col.f32.f16.f16.f32 "
        "{%0,%1,%2,%3}, {%4,%5,%6,%7}, {%8,%9}, {%0,%1,%2,%3};"
        : "+f"(c[0]), "+f"(c[1]), "+f"(c[2]), "+f"(c[3])
        : "r"(a[0]), "r"(a[1]), "r"(a[2]), "r"(a[3]), "r"(b0), "r"(b1));
}

__device__ __forceinline__ void mma16816h(unsigned* c, const unsigned* a,
                                          unsigned b0, unsigned b1) {
    asm volatile(
        "mma.sync.aligned.m16n8k16.row.col.f16.f16.f16.f16 "
        "{%0,%1}, {%2,%3,%4,%5}, {%6,%7}, {%0,%1};"
        : "+r"(c[0]), "+r"(c[1])
        : "r"(a[0]), "r"(a[1]), "r"(a[2]), "r"(a[3]), "r"(b0), "r"(b1));
}

__device__ __forceinline__ unsigned h2exp2u(unsigned x) {
    unsigned y;
    asm("ex2.approx.f16x2 %0, %1;" : "=r"(y) : "r"(x));
    return y;
}

__device__ __forceinline__ void cp_async16(unsigned saddr, const void* gptr) {
    asm volatile("cp.async.cg.shared.global [%0], [%1], 16;" :: "r"(saddr), "l"(gptr));
}
#define CP_COMMIT() asm volatile("cp.async.commit_group;")

// ---------------------------------------------------------------------------
// prep kernel: weight convert + LayerNorm in ONE launch.
// grid = (2048, 5). grid.y 0..2: W{q,k,v} -> wqkv (512 blocks used);
// grid.y 3: Wo -> wo (512 blocks used); grid.y 4: LayerNorm (4 rows/block).
// ---------------------------------------------------------------------------
#define QSCALE 0.06376529780930452f   // 512^-0.5 * log2(e)

__global__ __launch_bounds__(128) void prep_kernel(
    const float* __restrict__ Wq, const float* __restrict__ Wk,
    const float* __restrict__ Wv, const float* __restrict__ Wo,
    __half* __restrict__ wqkv, __half* __restrict__ wo,
    const float* __restrict__ x, const float* __restrict__ gw,
    const float* __restrict__ bw, __half* __restrict__ xn)
{
    const int m = blockIdx.y;
    if (m < 4) {
        if (blockIdx.x >= 512) return;
        int i = (blockIdx.x * 128 + threadIdx.x) * 4;
        if (m < 3) {
            const float* src = (m == 0) ? Wq : (m == 1) ? Wk : Wv;
            float sc = (m == 0) ? QSCALE : 1.f;
            float4 v = *(const float4*)(src + i);
            int row = i >> 9, col = i & 511;
            __half2* dst = (__half2*)(wqkv + (size_t)row * QKVS + m * 512 + col);
            dst[0] = __floats2half2_rn(v.x * sc, v.y * sc);
            dst[1] = __floats2half2_rn(v.z * sc, v.w * sc);
        } else {
            float4 v = *(const float4*)(Wo + i);
            *(__half2*)(wo + i)     = __floats2half2_rn(v.x, v.y);
            *(__half2*)(wo + i + 2) = __floats2half2_rn(v.z, v.w);
        }
        return;
    }

    // LayerNorm: one warp per row, 4 rows per block
    const int warp = threadIdx.x >> 5;
    const int lane = threadIdx.x & 31;
    const int row  = blockIdx.x * 4 + warp;
    const float* xr = x + (size_t)row * DIM;

    float v[16];
    float s = 0.f, ss = 0.f;
#pragma unroll
    for (int i = 0; i < 4; i++) {
        float4 v4 = *(const float4*)(xr + lane * 4 + i * 128);
        v[i*4+0] = v4.x; v[i*4+1] = v4.y; v[i*4+2] = v4.z; v[i*4+3] = v4.w;
        s  += v4.x + v4.y + v4.z + v4.w;
        ss += v4.x*v4.x + v4.y*v4.y + v4.z*v4.z + v4.w*v4.w;
    }
#pragma unroll
    for (int o = 16; o; o >>= 1) {
        s  += __shfl_xor_sync(0xffffffffu, s,  o);
        ss += __shfl_xor_sync(0xffffffffu, ss, o);
    }
    float mu   = s * (1.f / DIM);
    float var  = ss * (1.f / DIM) - mu * mu;
    float rstd = rsqrtf(var + 1e-5f);

    __half* orow = xn + (size_t)row * DIM;
#pragma unroll
    for (int i = 0; i < 4; i++) {
        int d = lane * 4 + i * 128;
        float4 g4 = *(const float4*)(gw + d);
        float4 b4 = *(const float4*)(bw + d);
        __half2 h0 = __floats2half2_rn((v[i*4+0] - mu) * rstd * g4.x + b4.x,
                                       (v[i*4+1] - mu) * rstd * g4.y + b4.y);
        __half2 h1 = __floats2half2_rn((v[i*4+2] - mu) * rstd * g4.z + b4.z,
                                       (v[i*4+3] - mu) * rstd * g4.w + b4.w);
        *(__half2*)(orow + d)     = h0;
        *(__half2*)(orow + d + 2) = h1;
    }
}

// ---------------------------------------------------------------------------
// HGEMM v7: C = A[M,K] @ B[K,N], 128x128 tile, BK=64, 256 threads
// (8 warps: 2m x 4n, warp tile 64x32), 3-stage cp.async ring, f16 accum.
// __maxnreg__(120) (alone; conflicts with launch_bounds): RF margin so
// 2 CTAs fit (2x256x120=61.4K < 64K - alloc gap) -> 4 warps/SMSP of
// UNSYNCHRONIZED work.
// Ch fp16 out (direct h2 store), or Cf fp32 out with +bias +resid.
// ---------------------------------------------------------------------------
#define GBM 128
#define GBN 128
#define GBK 64
#define APITCH 72    // 64+8 halfs, 144B rows
#define BPITCH 136   // 128+8 halfs, 272B rows
#define HG_STAGE_H (GBM * APITCH + GBK * BPITCH)   // 17920 halfs
#define HG_SMEM    (3 * HG_STAGE_H * 2)            // 107520 B

__global__ __maxnreg__(120) void hgemm_kernel(
    const __half* __restrict__ A, const __half* __restrict__ B,
    __half* __restrict__ Ch, float* __restrict__ Cf,
    int M, int N, int K,
    const float* __restrict__ bias, const float* __restrict__ resid)
{
    extern __shared__ __half hsm[];

    const int tid  = threadIdx.x;
    const int warp = tid >> 5;
    const int lane = tid & 31;
    const int warp_m = warp >> 2;   // 0..1
    const int warp_n = warp & 3;    // 0..3
    const int row0 = blockIdx.y * GBM;
    const int col0 = blockIdx.x * GBN;

    const unsigned hbase = smem_u32(hsm);

    // f16 accumulators: [mi][nf][0]=rows g (2 cols packed), [1]=rows g+8
    unsigned acc[4][4][2];
#pragma unroll
    for (int mi = 0; mi < 4; mi++)
#pragma unroll
        for (int nf = 0; nf < 4; nf++) { acc[mi][nf][0] = 0u; acc[mi][nf][1] = 0u; }

    const int nk = K / GBK;   // 8

#define HG_LOAD(k0, s) do {                                                   \
    unsigned _ab = hbase + (s) * HG_STAGE_H * 2;                              \
    unsigned _bb = _ab + GBM * APITCH * 2;                                    \
    _Pragma("unroll")                                                         \
    for (int _j = 0; _j < 4; _j++) {                                          \
        int _i = tid + 256 * _j;                                              \
        int _ar = _i >> 3;                                                    \
        int _ac = (_i & 7) * 8;                                               \
        cp_async16(_ab + (_ar * APITCH + _ac) * 2,                            \
                   A + (size_t)(row0 + _ar) * K + (k0) + _ac);                \
        int _br = _i >> 4;                                                    \
        int _bc = (_i & 15) * 8;                                              \
        cp_async16(_bb + (_br * BPITCH + _bc) * 2,                            \
                   B + (size_t)((k0) + _br) * N + col0 + _bc);                \
    }                                                                         \
} while (0)

    HG_LOAD(0, 0);       CP_COMMIT();
    HG_LOAD(GBK, 1);     CP_COMMIT();

    const int a_rr = (lane & 15);
    const int a_cc = (lane & 16) ? 8 : 0;

    int st = 0, st_nxt = 2;
    for (int kt = 0; kt < nk; kt++) {
        asm volatile("cp.async.wait_group 1;");
        __syncthreads();

        if (kt + 2 < nk) {
            HG_LOAD((kt + 2) * GBK, st_nxt);
            CP_COMMIT();
        } else {
            CP_COMMIT();
        }

        const unsigned ab = hbase + st * HG_STAGE_H * 2;
        const unsigned bb = ab + GBM * APITCH * 2;

#pragma unroll
        for (int kc = 0; kc < 4; kc++) {
            unsigned af[4][4];
#pragma unroll
            for (int mi = 0; mi < 4; mi++) {
                unsigned addr = ab +
                    ((warp_m * 64 + mi * 16 + a_rr) * APITCH + kc * 16 + a_cc) * 2;
                LDSM4(af[mi][0], af[mi][1], af[mi][2], af[mi][3], addr);
            }
            unsigned b0, b1, b2, b3, c0, c1, c2, c3;
            unsigned baddr = bb +
                ((kc * 16 + a_rr) * BPITCH + warp_n * 32 + a_cc) * 2;
            LDSM4T(b0, b1, b2, b3, baddr);
            LDSM4T(c0, c1, c2, c3, baddr + 32);   // +16 halfs
#pragma unroll
            for (int mi = 0; mi < 4; mi++) {
                mma16816h(acc[mi][0], af[mi], b0, b1);
                mma16816h(acc[mi][1], af[mi], b2, b3);
                mma16816h(acc[mi][2], af[mi], c0, c1);
                mma16816h(acc[mi][3], af[mi], c2, c3);
            }
        }
        st = (st == 2) ? 0 : st + 1;
        st_nxt = (st_nxt == 2) ? 0 : st_nxt + 1;
    }
#undef HG_LOAD

    const int g  = lane >> 2;
    const int tg = lane & 3;
#pragma unroll
    for (int mi = 0; mi < 4; mi++) {
        int r0 = row0 + warp_m * 64 + mi * 16 + g;
        int r1 = r0 + 8;
#pragma unroll
        for (int nf = 0; nf < 4; nf++) {
            int c = col0 + warp_n * 32 + nf * 8 + tg * 2;
            if (Cf) {
                float2 f0 = __half22float2(*(__half2*)&acc[mi][nf][0]);
                float2 f1 = __half22float2(*(__half2*)&acc[mi][nf][1]);
                float2 o0, o1;
                o0.x = f0.x + bias[c]     + resid[(size_t)r0 * N + c];
                o0.y = f0.y + bias[c + 1] + resid[(size_t)r0 * N + c + 1];
                o1.x = f1.x + bias[c]     + resid[(size_t)r1 * N + c];
                o1.y = f1.y + bias[c + 1] + resid[(size_t)r1 * N + c + 1];
                *(float2*)(Cf + (size_t)r0 * N + c) = o0;
                *(float2*)(Cf + (size_t)r1 * N + c) = o1;
            } else {
                *(unsigned*)(Ch + (size_t)r0 * N + c) = acc[mi][nf][0];
                *(unsigned*)(Ch + (size_t)r1 * N + c) = acc[mi][nf][1];
            }
        }
    }
}

// ---------------------------------------------------------------------------
// Flash attention v6 (round-9 winner, unchanged):
// 128 threads = 4 warps, 32 queries/warp (128 q/CTA). Each K/V B-fragment
// feeds TWO A-fragments. Fixed-max softmax via ex2.f16x2 on f16-accum S
// frags, l via P @ ones MMA, 3-stage cp.async KV ring, 3 CTAs/SM.
// ---------------------------------------------------------------------------
#define PITCH   72
#define BIAS_H2 0xC5C5C5C5u   // half2(-5.7695 ~ -4*log2e) uniform -> cancels
#define ONES2   0x3C003C00u
#define FLASH_SMEM (3 * 2 * 64 * PITCH * 2)   // 55296 B

__global__ __launch_bounds__(128, 3) void flash_mma_kernel(
    const __half* __restrict__ qkv, __half* __restrict__ Op)
{
    extern __shared__ __half fsm[];

    const int tid  = threadIdx.x;
    const int warp = tid >> 5;
    const int lane = tid & 31;
    const int g    = lane >> 2;
    const int tg   = lane & 3;

    const int m0 = blockIdx.x * 128;
    const int h  = blockIdx.y;
    const int b  = blockIdx.z;

    const size_t rowbase = (size_t)b * SEQ;
    const int    colbase = h * DH;

    const __half* Qg = qkv + colbase;
    const __half* Kg = qkv + 512  + colbase;
    const __half* Vg = qkv + 1024 + colbase;

    const int r16 = tid >> 3;         // 0..15
    const int c8  = (tid & 7) * 8;

    // ---- Q tile: 128 rows into ring area (transient) ----
#pragma unroll
    for (int p = 0; p < 8; p++) {
        int row = p * 16 + r16;
        cp_async16(smem_u32(fsm + (size_t)row * PITCH + c8),
                   Qg + (rowbase + m0 + row) * QKVS + c8);
    }
    CP_COMMIT();
    asm volatile("cp.async.wait_group 0;");
    __syncthreads();

    unsigned qf[2][4][4];
    {
        int cc_off = (lane & 16) ? 8 : 0;
#pragma unroll
        for (int mi = 0; mi < 2; mi++) {
            int rr = warp * 32 + mi * 16 + (lane & 15);
#pragma unroll
            for (int kc = 0; kc < 4; kc++) {
                unsigned addr = smem_u32(fsm + (size_t)rr * PITCH + kc * 16 + cc_off);
                LDSM4(qf[mi][kc][0], qf[mi][kc][1], qf[mi][kc][2], qf[mi][kc][3], addr);
            }
        }
    }
    __syncthreads();   // qf extracted before KV overwrites

    float o[2][8][4];
#pragma unroll
    for (int mi = 0; mi < 2; mi++)
#pragma unroll
        for (int nc = 0; nc < 8; nc++)
#pragma unroll
            for (int j = 0; j < 4; j++) o[mi][nc][j] = 0.f;
    float lf[2][4] = {{0.f,0.f,0.f,0.f},{0.f,0.f,0.f,0.f}};

    const int k_rr_off = (lane & 7) + ((lane & 16) ? 8 : 0);
    const int k_cc_off = (lane & 8) ? 8 : 0;
    const int v_rr_off = (lane & 15);
    const int v_cc_off = (lane & 16) ? 8 : 0;

    const int NT = SEQ / 64;   // 32

    // prologue: tiles 0,1 into stages 0,1
#pragma unroll
    for (int pt = 0; pt < 2; pt++) {
#pragma unroll
        for (int p = 0; p < 4; p++) {
            int row = p * 16 + r16;
            size_t goff = (rowbase + pt * 64 + row) * QKVS + c8;
            cp_async16(smem_u32(fsm + ((size_t)(pt * 2 + 0) * 64 + row) * PITCH + c8),
                       Kg + goff);
            cp_async16(smem_u32(fsm + ((size_t)(pt * 2 + 1) * 64 + row) * PITCH + c8),
                       Vg + goff);
        }
        CP_COMMIT();
    }

    for (int kt = 0; kt < NT; kt++) {
        const int st = kt % 3;
        asm volatile("cp.async.wait_group 1;");
        __syncthreads();

        if (kt + 2 < NT) {
            const int sn = (kt + 2) % 3;
            const int n2 = (kt + 2) * 64;
#pragma unroll
            for (int p = 0; p < 4; p++) {
                int row = p * 16 + r16;
                size_t goff = (rowbase + n2 + row) * QKVS + c8;
                cp_async16(smem_u32(fsm + ((size_t)(sn * 2 + 0) * 64 + row) * PITCH + c8),
                           Kg + goff);
                cp_async16(smem_u32(fsm + ((size_t)(sn * 2 + 1) * 64 + row) * PITCH + c8),
                           Vg + goff);
            }
            CP_COMMIT();
        } else {
            CP_COMMIT();
        }

        const __half* Kst = fsm + (size_t)(st * 2 + 0) * 64 * PITCH;
        const __half* Vst = fsm + (size_t)(st * 2 + 1) * 64 * PITCH;

        // S + exp per key-group (keeps S liveness to 8 regs)
        unsigned pf[2][4][4];
#pragma unroll
        for (int kg = 0; kg < 4; kg++) {
            unsigned shl[2][2][2];
#pragma unroll
            for (int mi = 0; mi < 2; mi++) {
                shl[mi][0][0] = BIAS_H2; shl[mi][0][1] = BIAS_H2;
                shl[mi][1][0] = BIAS_H2; shl[mi][1][1] = BIAS_H2;
            }
#pragma unroll
            for (int kc = 0; kc < 4; kc++) {
                unsigned kb0, kb1, kb2, kb3;
                unsigned addr = smem_u32(
                    Kst + (size_t)(kg * 16 + k_rr_off) * PITCH + kc * 16 + k_cc_off);
                LDSM4(kb0, kb1, kb2, kb3, addr);
                mma16816h(shl[0][0], qf[0][kc], kb0, kb1);
                mma16816h(shl[0][1], qf[0][kc], kb2, kb3);
                mma16816h(shl[1][0], qf[1][kc], kb0, kb1);
                mma16816h(shl[1][1], qf[1][kc], kb2, kb3);
            }
#pragma unroll
            for (int mi = 0; mi < 2; mi++) {
                pf[mi][kg][0] = h2exp2u(shl[mi][0][0]);
                pf[mi][kg][1] = h2exp2u(shl[mi][0][1]);
                pf[mi][kg][2] = h2exp2u(shl[mi][1][0]);
                pf[mi][kg][3] = h2exp2u(shl[mi][1][1]);
                mma16816(lf[mi], pf[mi][kg], ONES2, ONES2);
            }
        }

        // O += P @ V (V fragment reused across mi)
#pragma unroll
        for (int kc = 0; kc < 4; kc++) {
#pragma unroll
            for (int dg = 0; dg < 4; dg++) {
                unsigned vb0, vb1, vb2, vb3;
                unsigned addr = smem_u32(
                    Vst + (size_t)(kc * 16 + v_rr_off) * PITCH + dg * 16 + v_cc_off);
                LDSM4T(vb0, vb1, vb2, vb3, addr);
                mma16816(o[0][2 * dg + 0], pf[0][kc], vb0, vb1);
                mma16816(o[0][2 * dg + 1], pf[0][kc], vb2, vb3);
                mma16816(o[1][2 * dg + 0], pf[1][kc], vb0, vb1);
                mma16816(o[1][2 * dg + 1], pf[1][kc], vb2, vb3);
            }
        }
    }

#pragma unroll
    for (int mi = 0; mi < 2; mi++) {
        float inv0 = 1.f / lf[mi][0];
        float inv1 = 1.f / lf[mi][2];
        int row0 = m0 + warp * 32 + mi * 16 + g;
        int row1 = row0 + 8;
#pragma unroll
        for (int nc = 0; nc < 8; nc++) {
            int col = colbase + nc * 8 + tg * 2;
            *(__half2*)(Op + (rowbase + row0) * HID + col) =
                __floats2half2_rn(o[mi][nc][0] * inv0, o[mi][nc][1] * inv0);
            *(__half2*)(Op + (rowbase + row1) * HID + col) =
                __floats2half2_rn(o[mi][nc][2] * inv1, o[mi][nc][3] * inv1);
        }
    }
}

// ---------------------------------------------------------------------------
extern "C" void kernel_launch(void* const* d_in, const int* in_sizes, int n_in,
                              void* d_out, int out_size)
{
    const float* x    = (const float*)d_in[0];
    const float* ln_g = (const float*)d_in[1];
    const float* ln_b = (const float*)d_in[2];
    const float* Wq   = (const float*)d_in[3];
    const float* Wk   = (const float*)d_in[4];
    const float* Wv   = (const float*)d_in[5];
    const float* Wo   = (const float*)d_in[6];
    const float* bo   = (const float*)d_in[7];
    float* out = (float*)d_out;

    __half *xn, *qkv, *ao, *wqkv, *wo;
    cudaGetSymbolAddress((void**)&xn,   g_xn);
    cudaGetSymbolAddress((void**)&qkv,  g_qkv);
    cudaGetSymbolAddress((void**)&ao,   g_ao);
    cudaGetSymbolAddress((void**)&wqkv, g_wqkv);
    cudaGetSymbolAddress((void**)&wo,   g_wo);

    cudaFuncSetAttribute(flash_mma_kernel,
                         cudaFuncAttributeMaxDynamicSharedMemorySize, FLASH_SMEM);
    cudaFuncSetAttribute(hgemm_kernel,
                         cudaFuncAttributeMaxDynamicSharedMemorySize, HG_SMEM);

    // 0+1) weight convert + LayerNorm, single launch
    prep_kernel<<<dim3(2048, 5), 128>>>(Wq, Wk, Wv, Wo, wqkv, wo,
                                        x, ln_g, ln_b, xn);

    // 2) fused QKV projection: [8192,512] @ [512,1536]
    hgemm_kernel<<<dim3(QKVS / GBN, ROWS / GBM), 256, HG_SMEM>>>(
        xn, wqkv, qkv, nullptr, ROWS, QKVS, DIM, nullptr, nullptr);

    // 3) Flash attention -> fp16
    flash_mma_kernel<<<dim3(SEQ / 128, NH, BB), 128, FLASH_SMEM>>>(qkv, ao);

    // 4) Output projection + bias + residual (fp32 out)
    hgemm_kernel<<<dim3(DIM / GBN, ROWS / GBM), 256, HG_SMEM>>>(
        ao, wo, nullptr, out, ROWS, DIM, HID, bo, x);
}